// round 2
// baseline (speedup 1.0000x reference)
#include <cuda_runtime.h>
#include <cstdint>

// QuantLinear 4-bit matvec, GB300 (sm_103a)  — split-K + epilogue version
//   y[o] = bias[o] + scales[o] * sum_k x[k]*w[k,o] - zeros[o] * sum_k x[k]
//   w[r*8+j, o] = (qweight[r,o] >> 4j) & 0xF
//
// R1 post-mortem: 128 CTAs (<148 SMs), 8 warps/SM -> latency-starved (DRAM 32%).
// R2: grid (128,4) = 512 CTAs, 4-resident/SM. Integer partials to __device__
// scratch (distinct slot per k-block, no atomics, no init needed), small
// epilogue kernel reduces + applies scale/zero/bias. x quantized to int16
// (scale 6553), nibbles extracted as packed u8 via 2 LOP3 masks, accumulated
// with 4x dp2a per word (integer-exact, deterministic).

#define K_IN    8192
#define N_OUT   8192
#define RW      1024           // qweight rows
#define KSPLIT  4
#define RW_BLK  (RW / KSPLIT)  // 256 rows per k-block
#define XSF     6553.0f

__device__ int g_part[KSPLIT][N_OUT];   // int partials; fully written each launch

__device__ __forceinline__ int dp2a_lo(int a, unsigned b, int c) {
    int d;
    asm("dp2a.lo.s32.u32 %0, %1, %2, %3;" : "=r"(d) : "r"(a), "r"(b), "r"(c));
    return d;
}
__device__ __forceinline__ int dp2a_hi(int a, unsigned b, int c) {
    int d;
    asm("dp2a.hi.s32.u32 %0, %1, %2, %3;" : "=r"(d) : "r"(a), "r"(b), "r"(c));
    return d;
}

__global__ __launch_bounds__(256, 4)
void qlin4_main(const float* __restrict__ x,
                const uint4* __restrict__ qw)      // [RW, N_OUT/4]
{
    // Packed int16 x for this k-block, dp2a byte-lane order:
    // group g: sxp[g] = { (x0|x2), (x4|x6), (x1|x3), (x5|x7) }
    __shared__ int4 sxp[RW_BLK];        // 4 KB
    __shared__ int4 sred4[16 * 16];     // 4 KB: [kslice][o-quad] partials

    const int tid = threadIdx.x;
    const int kb  = blockIdx.y;

    // ---- Phase 1: quantize + pack this block's 2048-value x chunk ----
    {
        const int g = tid;                                   // one 8-group per thread
        const float4* xp4 = (const float4*)x + (kb * RW_BLK + g) * 2;
        float4 a = __ldg(xp4);
        float4 b = __ldg(xp4 + 1);
        int q0 = __float2int_rn(a.x * XSF);
        int q1 = __float2int_rn(a.y * XSF);
        int q2 = __float2int_rn(a.z * XSF);
        int q3 = __float2int_rn(a.w * XSF);
        int q4 = __float2int_rn(b.x * XSF);
        int q5 = __float2int_rn(b.y * XSF);
        int q6 = __float2int_rn(b.z * XSF);
        int q7 = __float2int_rn(b.w * XSF);
        int4 p;
        p.x = (q0 & 0xFFFF) | (q2 << 16);
        p.y = (q4 & 0xFFFF) | (q6 << 16);
        p.z = (q1 & 0xFFFF) | (q3 << 16);
        p.w = (q5 & 0xFFFF) | (q7 << 16);
        sxp[g] = p;
    }
    __syncthreads();

    // ---- Phase 2: stream qweight rows [kb*256, kb*256+256) ----
    // oq in [0,16): uint4 column (4 outputs); ks in [0,16): 16-row K slice.
    // Half-warp covers 16 consecutive uint4 columns -> 256B contiguous.
    const int oq  = tid & 15;
    const int ks  = tid >> 4;
    const int col = blockIdx.x * 16 + oq;
    const uint4* p = qw + (size_t)(kb * RW_BLK + ks * 16) * (N_OUT / 4) + col;

    int a0 = 0, a1 = 0, a2 = 0, a3 = 0;
#pragma unroll 8
    for (int rr = 0; rr < 16; rr++) {
        uint4 q = __ldg(p);
        p += N_OUT / 4;
        int4 xp = sxp[ks * 16 + rr];

        unsigned lo, hi;
        lo = q.x & 0x0F0F0F0Fu; hi = (q.x >> 4) & 0x0F0F0F0Fu;
        a0 = dp2a_lo(xp.x, lo, a0); a0 = dp2a_hi(xp.y, lo, a0);
        a0 = dp2a_lo(xp.z, hi, a0); a0 = dp2a_hi(xp.w, hi, a0);

        lo = q.y & 0x0F0F0F0Fu; hi = (q.y >> 4) & 0x0F0F0F0Fu;
        a1 = dp2a_lo(xp.x, lo, a1); a1 = dp2a_hi(xp.y, lo, a1);
        a1 = dp2a_lo(xp.z, hi, a1); a1 = dp2a_hi(xp.w, hi, a1);

        lo = q.z & 0x0F0F0F0Fu; hi = (q.z >> 4) & 0x0F0F0F0Fu;
        a2 = dp2a_lo(xp.x, lo, a2); a2 = dp2a_hi(xp.y, lo, a2);
        a2 = dp2a_lo(xp.z, hi, a2); a2 = dp2a_hi(xp.w, hi, a2);

        lo = q.w & 0x0F0F0F0Fu; hi = (q.w >> 4) & 0x0F0F0F0Fu;
        a3 = dp2a_lo(xp.x, lo, a3); a3 = dp2a_hi(xp.y, lo, a3);
        a3 = dp2a_lo(xp.z, hi, a3); a3 = dp2a_hi(xp.w, hi, a3);
    }
    sred4[ks * 16 + oq] = make_int4(a0, a1, a2, a3);
    __syncthreads();

    // ---- Phase 3: reduce 16 k-slices, write integer partial ----
    if (tid < 64) {
        const int* sr = (const int*)sred4;   // 16 rows of 64 ints
        int s = 0;
#pragma unroll
        for (int k2 = 0; k2 < 16; k2++) s += sr[k2 * 64 + tid];
        g_part[kb][blockIdx.x * 64 + tid] = s;
    }
}

__global__ __launch_bounds__(256)
void qlin4_epi(const float* __restrict__ x,
               const float* __restrict__ scales,
               const float* __restrict__ zeros,
               const float* __restrict__ bias,
               float* __restrict__ out)
{
    __shared__ float sred[256];
    const int tid = threadIdx.x;

    // exact float xsum (x is 32KB, L2-hot after main kernel)
    float s = 0.f;
#pragma unroll
    for (int i = 0; i < K_IN / 256; i++) s += __ldg(x + i * 256 + tid);
    sred[tid] = s;
    __syncthreads();
#pragma unroll
    for (int off = 128; off > 0; off >>= 1) {
        if (tid < off) sred[tid] += sred[tid + off];
        __syncthreads();
    }
    const float xsum = sred[0];

    const int o = blockIdx.x * 256 + tid;
    int acc = g_part[0][o] + g_part[1][o] + g_part[2][o] + g_part[3][o];
    float xw = (float)acc * (1.0f / XSF);
    out[o] = __ldg(bias + o) + __ldg(scales + o) * xw - __ldg(zeros + o) * xsum;
}

extern "C" void kernel_launch(void* const* d_in, const int* in_sizes, int n_in,
                              void* d_out, int out_size)
{
    // metadata order: x, qweight, scales, zeros, bias
    const float* x      = (const float*)d_in[0];
    const uint4* qw     = (const uint4*)d_in[1];
    const float* scales = (const float*)d_in[2];
    const float* zeros  = (const float*)d_in[3];
    const float* bias   = (const float*)d_in[4];
    float* out          = (float*)d_out;

    qlin4_main<<<dim3(N_OUT / 64, KSPLIT), 256>>>(x, qw);
    qlin4_epi<<<N_OUT / 256, 256>>>(x, scales, zeros, bias, out);
}